// round 5
// baseline (speedup 1.0000x reference)
#include <cuda_runtime.h>

#define HID  128
#define NIN  64
#define NOUT 64
#define NB   256
#define NS   4096

typedef unsigned long long u64;

// xp[b][s][jp] = {xp[2jp], xp[2jp+1]} : x@Wx + bh + bx, j-pair packed. 512 MB.
__device__ u64 g_xp[NB][NS][HID / 2];
// hs[b][s][jp] = {h[2jp], h[2jp+1]}. 512 MB.
__device__ u64 g_hs[NB][NS][HID / 2];
// chunk carry
__device__ u64 g_h[NB][HID / 2];

__device__ __forceinline__ u64 ffma2(u64 a, u64 b, u64 c) {
    u64 d;
    asm("fma.rn.f32x2 %0, %1, %2, %3;" : "=l"(d) : "l"(a), "l"(b), "l"(c));
    return d;
}
__device__ __forceinline__ u64 fadd2(u64 a, u64 b) {
    u64 d;
    asm("add.rn.f32x2 %0, %1, %2;" : "=l"(d) : "l"(a), "l"(b));
    return d;
}
__device__ __forceinline__ u64 pack2(float x, float y) {
    u64 d;
    asm("mov.b64 %0, {%1, %2};" : "=l"(d) : "f"(x), "f"(y));
    return d;
}
__device__ __forceinline__ float2 unpack2(u64 v) {
    float2 r;
    asm("mov.b64 {%0, %1}, %2;" : "=f"(r.x), "=f"(r.y) : "l"(v));
    return r;
}
__device__ __forceinline__ u64 shfl_xor64(u64 v, int m) {
    return __shfl_xor_sync(0xffffffffu, v, m);
}
// skewed hbuf index: 2 u64 pad per 32-u64 block -> kq slices hit distinct banks
#define HB(k) ((k) + (((k) >> 5) << 1))

// ---------------------------------------------------------------------------
// Kernel 1: xp[b][s][jp] = x[b][s]@Wx + bh + bx  (j-pair packed u64)
// Grid (NS/16, NB), 256 threads: thread (jp = t>>2, iq = t&3).
// Skewed tile rows: logical i stored at i + 2*(i>>4); max index 69 -> dim 72.
// ---------------------------------------------------------------------------
__global__ void __launch_bounds__(256) xp_kernel(
    const float* __restrict__ x,  const float* __restrict__ Wx,
    const float* __restrict__ bh, const float* __restrict__ bx)
{
    __shared__ __align__(16) u64 xt[16][72];    // duplicated {x,x}, skewed
    __shared__ __align__(16) u64 xpt[16][64];   // result staging

    const int t  = threadIdx.x;
    const int jp = t >> 2;
    const int iq = t & 3;
    const int j0 = 2 * jp;
    const int b  = blockIdx.y;
    const int s0 = blockIdx.x * 16;

    u64 wxp[16];
#pragma unroll
    for (int m = 0; m < 16; m++) {
        int i = iq * 16 + m;
        wxp[m] = *(const u64*)(Wx + i * HID + j0);   // {Wx[i][j0], Wx[i][j0+1]}
    }
    u64 bias2 = 0;
    if (iq == 0) bias2 = pack2(bh[j0] + bx[j0], bh[j0 + 1] + bx[j0 + 1]);

    // Cooperative duplicated x tile load: 16 s x 64 i.
#pragma unroll
    for (int q = 0; q < 4; q++) {
        int idx = t + q * 256;
        int s = idx >> 6, i = idx & 63;
        float v = x[((long long)b * NS + s0 + s) * NIN + i];
        xt[s][i + ((i >> 4) << 1)] = pack2(v, v);
    }
    __syncthreads();

#pragma unroll 4
    for (int s = 0; s < 16; s++) {
        const u64* xrow = &xt[s][iq * 18];
        u64 accA = 0, accB = 0;
#pragma unroll
        for (int m = 0; m < 16; m += 2) {
            ulonglong2 xv = *(const ulonglong2*)(xrow + m);
            accA = ffma2(wxp[m],     xv.x, accA);
            accB = ffma2(wxp[m + 1], xv.y, accB);
        }
        u64 acc = fadd2(accA, accB);
        acc = fadd2(acc, shfl_xor64(acc, 1));
        acc = fadd2(acc, shfl_xor64(acc, 2));
        if (iq == 0) xpt[s][jp] = fadd2(acc, bias2);
    }
    __syncthreads();

#pragma unroll
    for (int q = 0; q < 4; q++) {
        int idx = t + q * 256;
        int s = idx >> 6, jj = idx & 63;
        g_xp[b][s0 + s][jj] = xpt[s][jj];
    }
}

// ---------------------------------------------------------------------------
// Kernel 2: recurrence chunk [s0,s1), s0/s1 % 4 == 0.
// Grid: 128 CTAs x 512 thr. Two independent 256-thread groups per CTA (one
// batch row each), synced with named barriers. Thread (jp = t>>2, kq = t&3):
// {h[2jp],h[2jp+1]} k-quarter partial; shfl_xor(1,2) reduces kq; ONE barrier
// per step. Wh pairs register-resident (64 regs). xp via 2-block smem ring
// (8-step LDG slack); h flushed to g_hs in coalesced 4-step blocks.
// ---------------------------------------------------------------------------
__global__ void __launch_bounds__(512, 1) rnn_rec_chunk(
    const float* __restrict__ Wh, int s0, int s1)
{
    __shared__ __align__(16) u64 hbuf[2][2][134];       // [grp][buf][skewed 128]
    __shared__ __align__(16) u64 xpring[2][2][4][64];   // [grp][slot][st][jp]
    __shared__ __align__(16) u64 hout[2][2][4][64];     // [grp][slot][st][jp]

    const int tid = threadIdx.x;
    const int gid = tid >> 8;
    const int t   = tid & 255;
    const int jp  = t >> 2;
    const int kq  = t & 3;
    const int j0  = 2 * jp;
    const int b   = blockIdx.x * 2 + gid;
    const int bar = gid + 1;

    // Wh pair slice: 32 x u64 = 64 regs.
    u64 whd[32];
#pragma unroll
    for (int m = 0; m < 32; m++) {
        int k = kq * 32 + m;
        whd[m] = *(const u64*)(Wh + k * HID + j0);
    }

    // x stager mapping (all 256 threads of group): one u64 of a 4-step block.
    const int st_ld = t >> 6;
    const int jp_ld = t & 63;

    const int B0 = s0 >> 2;

    // Prologue: init h, stage xp block B0, prefetch block B0+1.
    if (kq == 0) {
        float2 h0 = make_float2(0.f, 0.f);
        if (s0 != 0) h0 = unpack2(g_h[b][jp]);
        ulonglong2 w2;
        w2.x = pack2(h0.x, h0.x);
        w2.y = pack2(h0.y, h0.y);
        *(ulonglong2*)&hbuf[gid][s0 & 1][HB(j0)] = w2;
    }
    xpring[gid][B0 & 1][st_ld][jp_ld] = g_xp[b][4 * B0 + st_ld][jp_ld];
    u64 xr = 0;
    if (4 * (B0 + 1) < NS) xr = g_xp[b][4 * (B0 + 1) + st_ld][jp_ld];
    asm volatile("bar.sync %0, 256;" :: "r"(bar) : "memory");

    for (int s = s0; s < s1; s++) {
        const int cur = s & 1, nxt = cur ^ 1;
        const int bc  = s >> 2, st = s & 3;

        if (st == 0) {
            // stage block bc+1, prefetch bc+2, flush hout block bc-1
            xpring[gid][(bc + 1) & 1][st_ld][jp_ld] = xr;
            if (4 * (bc + 2) < NS) xr = g_xp[b][4 * (bc + 2) + st_ld][jp_ld];
            if (bc > B0)
                g_hs[b][4 * (bc - 1) + st_ld][jp_ld] = hout[gid][(bc - 1) & 1][st_ld][jp_ld];
        }

        const u64* hb = &hbuf[gid][cur][kq * 34];
        u64 accA = 0, accB = 0;
#pragma unroll
        for (int m = 0; m < 32; m += 2) {
            ulonglong2 hv = *(const ulonglong2*)(hb + m);   // {h_k,h_k},{h_k1,h_k1}
            accA = ffma2(whd[m],     hv.x, accA);
            accB = ffma2(whd[m + 1], hv.y, accB);
        }
        u64 acc = fadd2(accA, accB);
        acc = fadd2(acc, shfl_xor64(acc, 1));
        acc = fadd2(acc, shfl_xor64(acc, 2));

        if (kq == 0) {
            u64 xpv = xpring[gid][bc & 1][st][jp];
            float2 tv = unpack2(fadd2(acc, xpv));
            tv.x = fmaxf(tv.x, 0.f);
            tv.y = fmaxf(tv.y, 0.f);
            ulonglong2 w2;
            w2.x = pack2(tv.x, tv.x);
            w2.y = pack2(tv.y, tv.y);
            *(ulonglong2*)&hbuf[gid][nxt][HB(j0)] = w2;     // duplicated for next step
            hout[gid][bc & 1][st][jp] = pack2(tv.x, tv.y);  // compact for flush
            if (s == s1 - 1) g_h[b][jp] = pack2(tv.x, tv.y);
        }
        asm volatile("bar.sync %0, 256;" :: "r"(bar) : "memory");
    }

    // Tail flush of last block.
    {
        int bl = (s1 >> 2) - 1;
        g_hs[b][4 * bl + st_ld][jp_ld] = hout[gid][bl & 1][st_ld][jp_ld];
    }
}

// ---------------------------------------------------------------------------
// Kernel 3: out[b][s][o] = hs[b][s]@Wy + by.
// Grid (NS/16, NB), 256 threads: thread (o = t>>2, jq = t&3).
// ---------------------------------------------------------------------------
__global__ void __launch_bounds__(256) rnn_output(
    const float* __restrict__ Wy, const float* __restrict__ by,
    float* __restrict__ out)
{
    __shared__ __align__(16) u64   hst[16][72];   // skewed, max index 69
    __shared__ __align__(16) float ot[16][64];

    const int t  = threadIdx.x;
    const int o  = t >> 2;
    const int jq = t & 3;
    const int b  = blockIdx.y;
    const int s0 = blockIdx.x * 16;

    u64 wyp[16];
#pragma unroll
    for (int m = 0; m < 16; m++) {
        int jpp = jq * 16 + m;
        wyp[m] = pack2(Wy[(2 * jpp) * NOUT + o], Wy[(2 * jpp + 1) * NOUT + o]);
    }
    float byv = by[o];

#pragma unroll
    for (int q = 0; q < 4; q++) {
        int idx = t + q * 256;
        int s = idx >> 6, jj = idx & 63;
        hst[s][jj + ((jj >> 4) << 1)] = g_hs[b][s0 + s][jj];
    }
    __syncthreads();

#pragma unroll 4
    for (int s = 0; s < 16; s++) {
        const u64* hrow = &hst[s][jq * 18];
        u64 accA = 0, accB = 0;
#pragma unroll
        for (int m = 0; m < 16; m += 2) {
            ulonglong2 hv = *(const ulonglong2*)(hrow + m);
            accA = ffma2(wyp[m],     hv.x, accA);
            accB = ffma2(wyp[m + 1], hv.y, accB);
        }
        u64 acc = fadd2(accA, accB);
        acc = fadd2(acc, shfl_xor64(acc, 1));
        acc = fadd2(acc, shfl_xor64(acc, 2));
        if (jq == 0) {
            float2 a = unpack2(acc);
            ot[s][o] = a.x + a.y + byv;
        }
    }
    __syncthreads();

#pragma unroll
    for (int q = 0; q < 4; q++) {
        int idx = t + q * 256;
        int s = idx >> 6, oo = idx & 63;
        out[((long long)b * NS + s0 + s) * NOUT + oo] = ot[s][oo];
    }
}

extern "C" void kernel_launch(void* const* d_in, const int* in_sizes, int n_in,
                              void* d_out, int out_size)
{
    const float* x  = (const float*)d_in[0];
    const float* Wh = (const float*)d_in[1];
    const float* bh = (const float*)d_in[2];
    const float* bx = (const float*)d_in[4];
    const float* Wx = (const float*)d_in[3];
    const float* Wy = (const float*)d_in[5];
    const float* by = (const float*)d_in[6];
    float* out = (float*)d_out;

    xp_kernel<<<dim3(NS / 16, NB), 256>>>(x, Wx, bh, bx);
    rnn_rec_chunk<<<NB / 2, 512>>>(Wh,    0, 1364);
    rnn_rec_chunk<<<NB / 2, 512>>>(Wh, 1364, 2732);
    rnn_rec_chunk<<<NB / 2, 512>>>(Wh, 2732, 4096);
    rnn_output<<<dim3(NS / 16, NB), 256>>>(Wy, by, out);
}

// round 6
// speedup vs baseline: 1.1867x; 1.1867x over previous
#include <cuda_runtime.h>

#define HID  128
#define NIN  64
#define NOUT 64
#define NB   256
#define NS   4096

typedef unsigned long long u64;

// xp[b][s][jp] = {xp[2jp], xp[2jp+1]} : x@Wx + bh + bx, j-pair packed. 512 MB.
__device__ u64 g_xp[NB][NS][HID / 2];
// hs[b][s][jp] = {h[2jp], h[2jp+1]}. 512 MB.
__device__ u64 g_hs[NB][NS][HID / 2];
// chunk carry
__device__ u64 g_h[NB][HID / 2];

__device__ __forceinline__ u64 ffma2(u64 a, u64 b, u64 c) {
    u64 d;
    asm("fma.rn.f32x2 %0, %1, %2, %3;" : "=l"(d) : "l"(a), "l"(b), "l"(c));
    return d;
}
__device__ __forceinline__ u64 fadd2(u64 a, u64 b) {
    u64 d;
    asm("add.rn.f32x2 %0, %1, %2;" : "=l"(d) : "l"(a), "l"(b));
    return d;
}
__device__ __forceinline__ u64 pack2(float x, float y) {
    u64 d;
    asm("mov.b64 %0, {%1, %2};" : "=l"(d) : "f"(x), "f"(y));
    return d;
}
__device__ __forceinline__ float2 unpack2(u64 v) {
    float2 r;
    asm("mov.b64 {%0, %1}, %2;" : "=f"(r.x), "=f"(r.y) : "l"(v));
    return r;
}
__device__ __forceinline__ u64 shfl_xor64(u64 v, int m) {
    return __shfl_xor_sync(0xffffffffu, v, m);
}
// skewed hbuf index: 2 u64 pad per 32-u64 block -> kq slices hit distinct banks
#define HB(k) ((k) + (((k) >> 5) << 1))

// ---------------------------------------------------------------------------
// Kernel 1 (v2): xp[b][s][jp] = x[b][s]@Wx + bh + bx  (j-pair packed u64)
// Grid (NS/64, NB), 256 threads. Thread t: ih = t&1 (i-half, lane bit 0 so the
// reduce is shfl_xor(1)), jp = (t>>1)&63, sh = t>>7 (32 s each).
// x tile duplicated {x,x} u64, skewed rows (i -> i + 2*(i>>5), dim 68).
// Results written straight to g_xp by ih==0 lanes (coalesced 128B/warp).
// ---------------------------------------------------------------------------
__global__ void __launch_bounds__(256) xp_kernel(
    const float* __restrict__ x,  const float* __restrict__ Wx,
    const float* __restrict__ bh, const float* __restrict__ bx)
{
    __shared__ __align__(16) u64 xt[64][68];    // duplicated {x,x}, skewed

    const int t  = threadIdx.x;
    const int ih = t & 1;
    const int jp = (t >> 1) & 63;
    const int sh = t >> 7;
    const int j0 = 2 * jp;
    const int b  = blockIdx.y;
    const int s0 = blockIdx.x * 64;

    u64 wxp[32];
#pragma unroll
    for (int m = 0; m < 32; m++) {
        int i = ih * 32 + m;
        wxp[m] = *(const u64*)(Wx + i * HID + j0);   // {Wx[i][j0], Wx[i][j0+1]}
    }
    const u64 bias2 = pack2(bh[j0] + bx[j0], bh[j0 + 1] + bx[j0 + 1]);

    // Cooperative duplicated x tile load: 64 s x 64 i.
#pragma unroll
    for (int q = 0; q < 16; q++) {
        int idx = t + q * 256;
        int s = idx >> 6, i = idx & 63;
        float v = x[((long long)b * NS + s0 + s) * NIN + i];
        xt[s][i + ((i >> 5) << 1)] = pack2(v, v);
    }
    __syncthreads();

#pragma unroll 4
    for (int ss = 0; ss < 32; ss++) {
        int s = sh * 32 + ss;
        const u64* xrow = &xt[s][ih * 34];
        u64 accA = 0, accB = 0;
#pragma unroll
        for (int m = 0; m < 32; m += 2) {
            ulonglong2 xv = *(const ulonglong2*)(xrow + m);
            accA = ffma2(wxp[m],     xv.x, accA);
            accB = ffma2(wxp[m + 1], xv.y, accB);
        }
        u64 acc = fadd2(accA, accB);
        acc = fadd2(acc, shfl_xor64(acc, 1));     // combine i-halves
        if (ih == 0)
            g_xp[b][s0 + s][jp] = fadd2(acc, bias2);
    }
}

// ---------------------------------------------------------------------------
// Kernel 2 (v2): recurrence chunk [s0,s1), s0/s1 % 4 == 0.
// Grid: 128 CTAs x 512 thr, two independent 256-thread groups (one batch row
// each, named barriers). Thread (jp = t>>2, kq = t&3). Changes vs R5:
//  - 4-step unrolled block loop: staging/prefetch hoisted to block head,
//    compile-time st kills the per-step `if (st==0)` branch.
//  - xp value pre-initialises the kq==0 accumulator (tail shortened).
//  - finalize STGs h straight to g_hs (hout buffer gone).
// ---------------------------------------------------------------------------
__global__ void __launch_bounds__(512, 1) rnn_rec_chunk(
    const float* __restrict__ Wh, int s0, int s1)
{
    __shared__ __align__(16) u64 hbuf[2][2][134];       // [grp][buf][skewed 128]
    __shared__ __align__(16) u64 xpring[2][2][4][64];   // [grp][slot][st][jp]

    const int tid = threadIdx.x;
    const int gid = tid >> 8;
    const int t   = tid & 255;
    const int jp  = t >> 2;
    const int kq  = t & 3;
    const int j0  = 2 * jp;
    const int b   = blockIdx.x * 2 + gid;
    const int bar = gid + 1;

    // Wh pair slice: 32 x u64 = 64 regs.
    u64 whd[32];
#pragma unroll
    for (int m = 0; m < 32; m++) {
        int k = kq * 32 + m;
        whd[m] = *(const u64*)(Wh + k * HID + j0);
    }

    const int st_ld = t >> 6;
    const int jp_ld = t & 63;
    const int B0 = s0 >> 2, B1 = s1 >> 2;

    // Prologue: init h (buffer 0: s0 is a multiple of 4), stage xp block B0,
    // prefetch block B0+1 into xr.
    if (kq == 0) {
        float2 h0 = make_float2(0.f, 0.f);
        if (s0 != 0) h0 = unpack2(g_h[b][jp]);
        ulonglong2 w2;
        w2.x = pack2(h0.x, h0.x);
        w2.y = pack2(h0.y, h0.y);
        *(ulonglong2*)&hbuf[gid][0][HB(j0)] = w2;
    }
    xpring[gid][B0 & 1][st_ld][jp_ld] = g_xp[b][4 * B0 + st_ld][jp_ld];
    u64 xr = 0;
    if (4 * (B0 + 1) < NS) xr = g_xp[b][4 * (B0 + 1) + st_ld][jp_ld];
    asm volatile("bar.sync %0, 256;" :: "r"(bar) : "memory");

    for (int bc = B0; bc < B1; bc++) {
        // Block head: stage xp block bc+1 (slot was last read in block bc-1,
        // ordered by that block's barriers), prefetch block bc+2.
        xpring[gid][(bc + 1) & 1][st_ld][jp_ld] = xr;
        if (4 * (bc + 2) < NS) xr = g_xp[b][4 * (bc + 2) + st_ld][jp_ld];

#pragma unroll
        for (int st = 0; st < 4; st++) {
            const int cur = st & 1, nxt = cur ^ 1;

            u64 xpv = xpring[gid][bc & 1][st][jp];
            u64 accA = (kq == 0) ? xpv : 0ull;
            u64 accB = 0;
            const u64* hb = &hbuf[gid][cur][kq * 34];
#pragma unroll
            for (int m = 0; m < 32; m += 2) {
                ulonglong2 hv = *(const ulonglong2*)(hb + m);
                accA = ffma2(whd[m],     hv.x, accA);
                accB = ffma2(whd[m + 1], hv.y, accB);
            }
            u64 acc = fadd2(accA, accB);
            acc = fadd2(acc, shfl_xor64(acc, 1));
            acc = fadd2(acc, shfl_xor64(acc, 2));

            if (kq == 0) {
                float2 tv = unpack2(acc);
                tv.x = fmaxf(tv.x, 0.f);
                tv.y = fmaxf(tv.y, 0.f);
                ulonglong2 w2;
                w2.x = pack2(tv.x, tv.x);
                w2.y = pack2(tv.y, tv.y);
                *(ulonglong2*)&hbuf[gid][nxt][HB(j0)] = w2;   // dup for next step
                u64 h2 = pack2(tv.x, tv.y);
                g_hs[b][4 * bc + st][jp] = h2;                // direct compact STG
                if (st == 3 && bc == B1 - 1) g_h[b][jp] = h2; // chunk carry
            }
            asm volatile("bar.sync %0, 256;" :: "r"(bar) : "memory");
        }
    }
}

// ---------------------------------------------------------------------------
// Kernel 3: out[b][s][o] = hs[b][s]@Wy + by.  (unchanged, known-correct)
// ---------------------------------------------------------------------------
__global__ void __launch_bounds__(256) rnn_output(
    const float* __restrict__ Wy, const float* __restrict__ by,
    float* __restrict__ out)
{
    __shared__ __align__(16) u64   hst[16][72];   // skewed, max index 69
    __shared__ __align__(16) float ot[16][64];

    const int t  = threadIdx.x;
    const int o  = t >> 2;
    const int jq = t & 3;
    const int b  = blockIdx.y;
    const int s0 = blockIdx.x * 16;

    u64 wyp[16];
#pragma unroll
    for (int m = 0; m < 16; m++) {
        int jpp = jq * 16 + m;
        wyp[m] = pack2(Wy[(2 * jpp) * NOUT + o], Wy[(2 * jpp + 1) * NOUT + o]);
    }
    float byv = by[o];

#pragma unroll
    for (int q = 0; q < 4; q++) {
        int idx = t + q * 256;
        int s = idx >> 6, jj = idx & 63;
        hst[s][jj + ((jj >> 4) << 1)] = g_hs[b][s0 + s][jj];
    }
    __syncthreads();

#pragma unroll 4
    for (int s = 0; s < 16; s++) {
        const u64* hrow = &hst[s][jq * 18];
        u64 accA = 0, accB = 0;
#pragma unroll
        for (int m = 0; m < 16; m += 2) {
            ulonglong2 hv = *(const ulonglong2*)(hrow + m);
            accA = ffma2(wyp[m],     hv.x, accA);
            accB = ffma2(wyp[m + 1], hv.y, accB);
        }
        u64 acc = fadd2(accA, accB);
        acc = fadd2(acc, shfl_xor64(acc, 1));
        acc = fadd2(acc, shfl_xor64(acc, 2));
        if (jq == 0) {
            float2 a = unpack2(acc);
            ot[s][o] = a.x + a.y + byv;
        }
    }
    __syncthreads();

#pragma unroll
    for (int q = 0; q < 4; q++) {
        int idx = t + q * 256;
        int s = idx >> 6, oo = idx & 63;
        out[((long long)b * NS + s0 + s) * NOUT + oo] = ot[s][oo];
    }
}

extern "C" void kernel_launch(void* const* d_in, const int* in_sizes, int n_in,
                              void* d_out, int out_size)
{
    const float* x  = (const float*)d_in[0];
    const float* Wh = (const float*)d_in[1];
    const float* bh = (const float*)d_in[2];
    const float* Wx = (const float*)d_in[3];
    const float* bx = (const float*)d_in[4];
    const float* Wy = (const float*)d_in[5];
    const float* by = (const float*)d_in[6];
    float* out = (float*)d_out;

    xp_kernel<<<dim3(NS / 64, NB), 256>>>(x, Wx, bh, bx);
    rnn_rec_chunk<<<NB / 2, 512>>>(Wh,    0, 1364);
    rnn_rec_chunk<<<NB / 2, 512>>>(Wh, 1364, 2732);
    rnn_rec_chunk<<<NB / 2, 512>>>(Wh, 2732, 4096);
    rnn_output<<<dim3(NS / 16, NB), 256>>>(Wy, by, out);
}